// round 6
// baseline (speedup 1.0000x reference)
#include <cuda_runtime.h>
#include <cuda_bf16.h>
#include <math.h>
#include <stdint.h>

// Problem constants
#define BB   256      // batch
#define TT   256      // time steps
#define ID   256      // input dim
#define HH   1024     // hidden dim
#define GG   4096     // 4*H gates

// Step-kernel tiling
#define KC          64                 // K chunk
#define NCH         (HH / KC)          // 16 chunks
// smem: A stages 2 x 16KB (hi8K+lo8K), B stages 2 x 32KB (hi16K+lo16K)
#define A_STAGE     16384
#define B_BASE      32768
#define B_STAGE     32768
#define DYN_SMEM    98304              // 96 KB
// Pre-GEMM: 2 stages x 64KB (Ahi16 Alo16 Bhi16 Blo16)
#define PRE_STAGE   65536
#define PRE_SMEM    131072

typedef unsigned long long ull;

// Scratch (device globals: allocation-free rule)
__device__ float g_pre[(size_t)BB * TT * GG];        // 1 GiB input-gate precompute
__device__ __nv_bfloat16 g_ut_hi[(size_t)GG * HH];   // U^T split hi [4096][1024]
__device__ __nv_bfloat16 g_ut_lo[(size_t)GG * HH];   // U^T split lo
__device__ __nv_bfloat16 g_wt_hi[GG * ID];           // folded W^T split hi [4096][256]
__device__ __nv_bfloat16 g_wt_lo[GG * ID];           // folded W^T split lo
__device__ __nv_bfloat16 g_x_hi[(size_t)BB * TT * ID];   // X split hi
__device__ __nv_bfloat16 g_x_lo[(size_t)BB * TT * ID];   // X split lo
__device__ __nv_bfloat16 g_hbf_hi[2][BB * HH];       // h ping-pong bf16 hi
__device__ __nv_bfloat16 g_hbf_lo[2][BB * HH];       // h ping-pong bf16 lo
__device__ unsigned int g_bar4[4][32];               // per-mt barriers (padded)

// ---------------------------------------------------------------------------
// helpers
// ---------------------------------------------------------------------------
__device__ __forceinline__ float fast_sigmoid(float x) {
    float e = __expf(-x);
    return __fdividef(1.0f, 1.0f + e);
}
__device__ __forceinline__ float fast_tanh(float x) {
    float e = __expf(2.0f * x);
    return 1.0f - __fdividef(2.0f, e + 1.0f);
}
__device__ __forceinline__ void cp_async16(uint32_t dst, const void* src) {
    asm volatile("cp.async.cg.shared.global [%0], [%1], 16;" :: "r"(dst), "l"(src));
}
__device__ __forceinline__ void ldsm_x4(uint32_t* r, uint32_t addr) {
    asm volatile("ldmatrix.sync.aligned.m8n8.x4.shared.b16 {%0,%1,%2,%3}, [%4];"
                 : "=r"(r[0]), "=r"(r[1]), "=r"(r[2]), "=r"(r[3]) : "r"(addr));
}
__device__ __forceinline__ void ldsm_x2(uint32_t* r, uint32_t addr) {
    asm volatile("ldmatrix.sync.aligned.m8n8.x2.shared.b16 {%0,%1}, [%2];"
                 : "=r"(r[0]), "=r"(r[1]) : "r"(addr));
}
__device__ __forceinline__ void mma_bf16(float* d, const uint32_t* a, const uint32_t* b) {
    asm volatile("mma.sync.aligned.m16n8k16.row.col.f32.bf16.bf16.f32 "
                 "{%0,%1,%2,%3}, {%4,%5,%6,%7}, {%8,%9}, {%0,%1,%2,%3};"
                 : "+f"(d[0]), "+f"(d[1]), "+f"(d[2]), "+f"(d[3])
                 : "r"(a[0]), "r"(a[1]), "r"(a[2]), "r"(a[3]), "r"(b[0]), "r"(b[1]));
}

// ---------------------------------------------------------------------------
// Kernel A: fold Wy into W row 255, transpose, bf16-split -> g_wt_hi/lo[g][k]
// ---------------------------------------------------------------------------
__global__ void wt_split_kernel(const float* __restrict__ W,
                                const float* __restrict__ Wy) {
    __shared__ float tile[32][33];
    const int kb = blockIdx.x * 32;
    const int gb = blockIdx.y * 32;
    const int tx = threadIdx.x & 31;
    const int ty = threadIdx.x >> 5;
#pragma unroll
    for (int i = 0; i < 32; i += 8) {
        int krow = kb + ty + i;
        float v = W[(size_t)krow * GG + gb + tx];
        if (krow == ID - 1) v += Wy[gb + tx];
        tile[ty + i][tx] = v;
    }
    __syncthreads();
#pragma unroll
    for (int i = 0; i < 32; i += 8) {
        int g = gb + ty + i;
        int k = kb + tx;
        float v = tile[tx][ty + i];
        __nv_bfloat16 hi = __float2bfloat16(v);
        __nv_bfloat16 lo = __float2bfloat16(v - __bfloat162float(hi));
        g_wt_hi[g * ID + k] = hi;
        g_wt_lo[g * ID + k] = lo;
    }
}

// ---------------------------------------------------------------------------
// Kernel B: U^T bf16 split
// ---------------------------------------------------------------------------
__global__ void u_split_kernel(const float* __restrict__ U) {
    __shared__ float tile[32][33];
    const int kb = blockIdx.x * 32;
    const int gb = blockIdx.y * 32;
    const int tx = threadIdx.x & 31;
    const int ty = threadIdx.x >> 5;
#pragma unroll
    for (int i = 0; i < 32; i += 8)
        tile[ty + i][tx] = U[(size_t)(kb + ty + i) * GG + gb + tx];
    __syncthreads();
#pragma unroll
    for (int i = 0; i < 32; i += 8) {
        int g = gb + ty + i;
        int k = kb + tx;
        float v = tile[tx][ty + i];
        __nv_bfloat16 hi = __float2bfloat16(v);
        __nv_bfloat16 lo = __float2bfloat16(v - __bfloat162float(hi));
        g_ut_hi[(size_t)g * HH + k] = hi;
        g_ut_lo[(size_t)g * HH + k] = lo;
    }
}

// ---------------------------------------------------------------------------
// Kernel C: X bf16 split
// ---------------------------------------------------------------------------
__global__ void x_split_kernel(const float* __restrict__ X) {
    size_t i4 = (size_t)blockIdx.x * blockDim.x + threadIdx.x;
    float4 v = *(const float4*)(X + i4 * 4);
    float f[4] = {v.x, v.y, v.z, v.w};
    __nv_bfloat16 hi[4], lo[4];
#pragma unroll
    for (int e = 0; e < 4; ++e) {
        hi[e] = __float2bfloat16(f[e]);
        lo[e] = __float2bfloat16(f[e] - __bfloat162float(hi[e]));
    }
    *(__nv_bfloat162*)(g_x_hi + i4 * 4)     = __nv_bfloat162(hi[0], hi[1]);
    *(__nv_bfloat162*)(g_x_hi + i4 * 4 + 2) = __nv_bfloat162(hi[2], hi[3]);
    *(__nv_bfloat162*)(g_x_lo + i4 * 4)     = __nv_bfloat162(lo[0], lo[1]);
    *(__nv_bfloat162*)(g_x_lo + i4 * 4 + 2) = __nv_bfloat162(lo[2], lo[3]);
}

// ---------------------------------------------------------------------------
// Kernel D: tensorized pre-GEMM, 2-stage pipelined.
// g_pre[m, g] = X[m,:] @ Wf[:, g] + bias[g]; CTA 128m x 128n, 4 K-chunks of 64.
// ---------------------------------------------------------------------------
__global__ __launch_bounds__(256, 1) void pre_gemm_mma(
    const float* __restrict__ bias) {
    extern __shared__ char dsm[];
    const uint32_t smem0 = (uint32_t)__cvta_generic_to_shared(dsm);

    const int tid = threadIdx.x;
    const int wid = tid >> 5;
    const int lane = tid & 31;
    const int mwarp = wid >> 1;
    const int nwarp = wid & 1;
    const int m0 = blockIdx.y * 128;
    const int n0 = blockIdx.x * 128;

    float acc[2][8][4];
#pragma unroll
    for (int mb = 0; mb < 2; ++mb)
#pragma unroll
        for (int nb = 0; nb < 8; ++nb)
#pragma unroll
            for (int r = 0; r < 4; ++r) acc[mb][nb][r] = 0.f;

    auto issue = [&](int kb, int s) {
        const int k0 = kb * KC;
        const uint32_t sb = smem0 + s * PRE_STAGE;
#pragma unroll
        for (int i = 0; i < 8; ++i) {
            int idx = i * 256 + tid;
            int mat = idx >> 10;
            int row = (idx >> 3) & 127;
            int gk = idx & 7;
            const __nv_bfloat16* src = (mat ? g_x_lo : g_x_hi) +
                (size_t)(m0 + row) * ID + k0 + gk * 8;
            uint32_t dst = sb + mat * 16384 + row * 128 + ((gk ^ (row & 7)) << 4);
            cp_async16(dst, src);
        }
#pragma unroll
        for (int i = 0; i < 8; ++i) {
            int idx = i * 256 + tid;
            int mat = idx >> 10;
            int row = (idx >> 3) & 127;
            int gk = idx & 7;
            const __nv_bfloat16* src = (mat ? g_wt_lo : g_wt_hi) +
                (size_t)(n0 + row) * ID + k0 + gk * 8;
            uint32_t dst = sb + 32768 + mat * 16384 + row * 128 + ((gk ^ (row & 7)) << 4);
            cp_async16(dst, src);
        }
        asm volatile("cp.async.commit_group;" ::: "memory");
    };

    issue(0, 0);
    asm volatile("cp.async.wait_group 0;" ::: "memory");
    __syncthreads();

    for (int kb = 0; kb < ID / KC; ++kb) {
        const int s = kb & 1;
        if (kb + 1 < ID / KC) issue(kb + 1, s ^ 1);
        const uint32_t sA = smem0 + s * PRE_STAGE;
        const uint32_t sB = sA + 32768;
#pragma unroll
        for (int ks = 0; ks < KC / 16; ++ks) {
            uint32_t a_hi[2][4], a_lo[2][4];
#pragma unroll
            for (int mb = 0; mb < 2; ++mb) {
                uint32_t arow = mwarp * 32 + mb * 16 + (lane & 15);
                int gk = ks * 2 + (lane >> 4);
                uint32_t off = arow * 128 + ((gk ^ (arow & 7)) << 4);
                ldsm_x4(a_hi[mb], sA + off);
                ldsm_x4(a_lo[mb], sA + 16384 + off);
            }
#pragma unroll
            for (int nb = 0; nb < 8; ++nb) {
                uint32_t brow = nwarp * 64 + nb * 8 + (lane & 7);
                int gk = ks * 2 + ((lane >> 3) & 1);
                uint32_t off = brow * 128 + ((gk ^ (brow & 7)) << 4);
                uint32_t b_hi[2], b_lo[2];
                ldsm_x2(b_hi, sB + off);
                ldsm_x2(b_lo, sB + 16384 + off);
#pragma unroll
                for (int mb = 0; mb < 2; ++mb) {
                    mma_bf16(acc[mb][nb], a_hi[mb], b_hi);
                    mma_bf16(acc[mb][nb], a_hi[mb], b_lo);
                    mma_bf16(acc[mb][nb], a_lo[mb], b_hi);
                }
            }
        }
        asm volatile("cp.async.wait_group 0;" ::: "memory");
        __syncthreads();
    }

    // epilogue: + bias, store fp32
#pragma unroll
    for (int nb = 0; nb < 8; ++nb) {
        const int col = n0 + nwarp * 64 + nb * 8 + (lane & 3) * 2;
        float2 bv = *(const float2*)(bias + col);
#pragma unroll
        for (int mb = 0; mb < 2; ++mb)
#pragma unroll
            for (int rh = 0; rh < 2; ++rh) {
                int row = m0 + mwarp * 32 + mb * 16 + rh * 8 + (lane >> 2);
                float2 o = make_float2(acc[mb][nb][rh * 2] + bv.x,
                                       acc[mb][nb][rh * 2 + 1] + bv.y);
                *(float2*)(g_pre + (size_t)row * GG + col) = o;
            }
    }
}

// ---------------------------------------------------------------------------
// Kernel E: barrier init
// ---------------------------------------------------------------------------
__global__ void bar_init_kernel() {
    if (threadIdx.x < 128)
        ((unsigned int*)g_bar4)[threadIdx.x] = 0u;
}

// ---------------------------------------------------------------------------
// Kernel F: persistent LSTM. 128 CTAs (1/SM), per-mt barriers (32 CTAs each),
// decoupled A/B smem pipelines; B (U) prefetched across the step boundary.
// ---------------------------------------------------------------------------
__global__ __launch_bounds__(256, 1) void lstm_persistent(
    float* __restrict__ hidden,      // [B][T][H]
    float* __restrict__ c_state,     // [B][H]
    float* __restrict__ h_final) {   // [B][H]
    extern __shared__ char dsm[];
    const int tid = threadIdx.x;
    const int wid = tid >> 5;
    const int lane = tid & 31;
    const int jt = blockIdx.x;       // 0..31
    const int mt = blockIdx.y;       // 0..3
    const int mwarp = wid >> 1;      // 0..3
    const int jwarp = wid & 1;       // 0..1
    const uint32_t smem0 = (uint32_t)__cvta_generic_to_shared(dsm);

    // B loader: U^T rows for this jt (step-independent addresses)
    auto issue_B = [&](int c, int s) {
        const int k0 = c * KC;
        const uint32_t sb = smem0 + B_BASE + s * B_STAGE;
#pragma unroll
        for (int i = 0; i < 8; ++i) {
            int idx = i * 256 + tid;
            int mat = idx >> 10;
            int row = (idx >> 3) & 127;
            int gk = idx & 7;
            int grow = (row >> 5) * HH + jt * 32 + (row & 31);
            const __nv_bfloat16* src = (mat ? g_ut_lo : g_ut_hi) +
                (size_t)grow * HH + k0 + gk * 8;
            uint32_t dst = sb + mat * 16384 + row * 128 + ((gk ^ (row & 7)) << 4);
            cp_async16(dst, src);
        }
    };

    for (int t = 0; t < TT; ++t) {
        float acc[4][2][4];
#pragma unroll
        for (int g = 0; g < 4; ++g)
#pragma unroll
            for (int nb = 0; nb < 2; ++nb)
#pragma unroll
                for (int r = 0; r < 4; ++r) acc[g][nb][r] = 0.f;

        if (t > 0) {
            const __nv_bfloat16* hphi = g_hbf_hi[(t - 1) & 1];
            const __nv_bfloat16* hplo = g_hbf_lo[(t - 1) & 1];

            auto issue_A = [&](int c, int s) {
                const int k0 = c * KC;
                const uint32_t sb = smem0 + s * A_STAGE;
#pragma unroll
                for (int i = 0; i < 4; ++i) {
                    int idx = i * 256 + tid;
                    int mat = idx >> 9;
                    int row = (idx >> 3) & 63;
                    int gk = idx & 7;
                    const __nv_bfloat16* src = (mat ? hplo : hphi) +
                        (size_t)(mt * 64 + row) * HH + k0 + gk * 8;
                    uint32_t dst = sb + mat * 8192 + row * 128 + ((gk ^ (row & 7)) << 4);
                    cp_async16(dst, src);
                }
            };

            // chunk 0: B already resident (prefetched across step boundary);
            // only A chunk 0 is exposed after the barrier.
            issue_A(0, 0);
            asm volatile("cp.async.commit_group;" ::: "memory");
            asm volatile("cp.async.wait_group 0;" ::: "memory");
            __syncthreads();

            const uint32_t arow = mwarp * 16 + (lane & 15);
            const uint32_t brow_base = jwarp * 16 + (lane & 7);

            for (int c = 0; c < NCH; ++c) {
                const int s = c & 1;
                if (c + 1 < NCH) {
                    issue_A(c + 1, s ^ 1);
                    issue_B(c + 1, s ^ 1);
                } else {
                    issue_B(0, 0);    // next step's chunk 0 (U is step-invariant)
                }
                asm volatile("cp.async.commit_group;" ::: "memory");

                const uint32_t sA = smem0 + s * A_STAGE;
                const uint32_t sB = smem0 + B_BASE + s * B_STAGE;
#pragma unroll
                for (int ks = 0; ks < KC / 16; ++ks) {
                    uint32_t a_hi[4], a_lo[4];
                    {
                        int gk = ks * 2 + (lane >> 4);
                        uint32_t off = arow * 128 + ((gk ^ (arow & 7)) << 4);
                        ldsm_x4(a_hi, sA + off);
                        ldsm_x4(a_lo, sA + 8192 + off);
                    }
#pragma unroll
                    for (int g = 0; g < 4; ++g) {
#pragma unroll
                        for (int nb = 0; nb < 2; ++nb) {
                            uint32_t row = g * 32 + brow_base + nb * 8;
                            int gk = ks * 2 + ((lane >> 3) & 1);
                            uint32_t off = row * 128 + ((gk ^ (row & 7)) << 4);
                            uint32_t b_hi[2], b_lo[2];
                            ldsm_x2(b_hi, sB + off);
                            ldsm_x2(b_lo, sB + 16384 + off);
                            mma_bf16(acc[g][nb], a_hi, b_hi);
                            mma_bf16(acc[g][nb], a_hi, b_lo);
                            mma_bf16(acc[g][nb], a_lo, b_hi);
                        }
                    }
                }
                asm volatile("cp.async.wait_group 0;" ::: "memory");
                __syncthreads();
            }
        } else {
            // t == 0: no GEMM; just prefetch B chunk 0 for step 1.
            issue_B(0, 0);
            asm volatile("cp.async.commit_group;" ::: "memory");
        }

        // ---- fused cell-update epilogue ----
        const int b_base = mt * 64 + mwarp * 16 + (lane >> 2);
#pragma unroll
        for (int rh = 0; rh < 2; ++rh) {
            const int b = b_base + rh * 8;
            const float* prow = g_pre + ((size_t)b * TT + t) * GG;
            float* crow = c_state + (size_t)b * HH;
            float* hrow = hidden + ((size_t)b * TT + t) * HH;
            __nv_bfloat16* bh = g_hbf_hi[t & 1] + (size_t)b * HH;
            __nv_bfloat16* bl = g_hbf_lo[t & 1] + (size_t)b * HH;
#pragma unroll
            for (int nb = 0; nb < 2; ++nb) {
                const int j = jt * 32 + jwarp * 16 + nb * 8 + (lane & 3) * 2;
                float2 pi = *(const float2*)(prow + 0 * HH + j);
                float2 pf = *(const float2*)(prow + 1 * HH + j);
                float2 pg = *(const float2*)(prow + 2 * HH + j);
                float2 po = *(const float2*)(prow + 3 * HH + j);
                float2 co = (t > 0) ? *(const float2*)(crow + j)
                                    : make_float2(0.f, 0.f);
                const int r0 = rh * 2;
                float i0 = fast_sigmoid(acc[0][nb][r0]     + pi.x);
                float i1 = fast_sigmoid(acc[0][nb][r0 + 1] + pi.y);
                float f0 = fast_sigmoid(acc[1][nb][r0]     + pf.x);
                float f1 = fast_sigmoid(acc[1][nb][r0 + 1] + pf.y);
                float g0 = fast_tanh(acc[2][nb][r0]     + pg.x);
                float g1 = fast_tanh(acc[2][nb][r0 + 1] + pg.y);
                float o0 = fast_sigmoid(acc[3][nb][r0]     + po.x);
                float o1 = fast_sigmoid(acc[3][nb][r0 + 1] + po.y);
                float cn0 = f0 * co.x + i0 * g0;
                float cn1 = f1 * co.y + i1 * g1;
                float hn0 = o0 * fast_tanh(cn0);
                float hn1 = o1 * fast_tanh(cn1);
                *(float2*)(crow + j) = make_float2(cn0, cn1);
                *(float2*)(hrow + j) = make_float2(hn0, hn1);
                __nv_bfloat16 h0h = __float2bfloat16(hn0);
                __nv_bfloat16 h1h = __float2bfloat16(hn1);
                __nv_bfloat16 h0l = __float2bfloat16(hn0 - __bfloat162float(h0h));
                __nv_bfloat16 h1l = __float2bfloat16(hn1 - __bfloat162float(h1h));
                *(__nv_bfloat162*)(bh + j) = __nv_bfloat162(h0h, h1h);
                *(__nv_bfloat162*)(bl + j) = __nv_bfloat162(h0l, h1l);
                if (t == TT - 1)
                    *(float2*)(h_final + (size_t)b * HH + j) = make_float2(hn0, hn1);
            }
        }

        // ---- per-mt device barrier (32 CTAs) ----
        if (t < TT - 1) {
            __threadfence();
            __syncthreads();
            if (tid == 0) {
                atomicAdd(&g_bar4[mt][0], 1u);
                const unsigned target = 32u * (unsigned)(t + 1);
                while (atomicAdd(&g_bar4[mt][0], 0u) < target) {}
            }
            __syncthreads();
            __threadfence();
        }
    }
}

// ---------------------------------------------------------------------------
// Kernel G: y_pred[b] = h_final[b,:] . fc_w + fc_b
// ---------------------------------------------------------------------------
__global__ void fc_kernel(const float* __restrict__ h_final,
                          const float* __restrict__ fc_w,
                          const float* __restrict__ fc_b,
                          float* __restrict__ y_pred) {
    int b = blockIdx.x;
    int tid = threadIdx.x;
    float s = 0.f;
    for (int k = tid; k < HH; k += 256)
        s += h_final[b * HH + k] * fc_w[k];
#pragma unroll
    for (int off = 16; off > 0; off >>= 1)
        s += __shfl_down_sync(0xffffffffu, s, off);
    __shared__ float red[8];
    if ((tid & 31) == 0) red[tid >> 5] = s;
    __syncthreads();
    if (tid == 0) {
        float tot = 0.f;
#pragma unroll
        for (int w = 0; w < 8; ++w) tot += red[w];
        y_pred[b] = tot + fc_b[0];
    }
}

// ---------------------------------------------------------------------------
extern "C" void kernel_launch(void* const* d_in, const int* in_sizes, int n_in,
                              void* d_out, int out_size) {
    const float* X    = (const float*)d_in[0];
    const float* W    = (const float*)d_in[1];
    const float* U    = (const float*)d_in[2];
    const float* bias = (const float*)d_in[3];
    const float* Wy   = (const float*)d_in[4];
    const float* fc_w = (const float*)d_in[5];
    const float* fc_b = (const float*)d_in[6];

    float* out = (float*)d_out;
    // output layout: y_pred[256] | hidden_seq[B*T*H] | h_t[B*H] | c_t[B*H]
    float* y_pred  = out;
    float* hidden  = out + 256;
    float* h_final = hidden + (size_t)BB * TT * HH;
    float* c_state = h_final + (size_t)BB * HH;

    cudaFuncSetAttribute(lstm_persistent, cudaFuncAttributeMaxDynamicSharedMemorySize,
                         DYN_SMEM);
    cudaFuncSetAttribute(pre_gemm_mma, cudaFuncAttributeMaxDynamicSharedMemorySize,
                         PRE_SMEM);

    wt_split_kernel<<<dim3(ID / 32, GG / 32), 256>>>(W, Wy);
    u_split_kernel<<<dim3(HH / 32, GG / 32), 256>>>(U);
    x_split_kernel<<<(BB * TT * ID) / 4 / 256, 256>>>(X);
    pre_gemm_mma<<<dim3(GG / 128, (BB * TT) / 128), 256, PRE_SMEM>>>(bias);
    bar_init_kernel<<<1, 128>>>();
    lstm_persistent<<<dim3(HH / 32, BB / 64), 256, DYN_SMEM>>>(hidden, c_state,
                                                               h_final);
    fc_kernel<<<BB, 256>>>(h_final, fc_w, fc_b, y_pred);
}

// round 7
// speedup vs baseline: 1.1284x; 1.1284x over previous
#include <cuda_runtime.h>
#include <cuda_bf16.h>
#include <math.h>
#include <stdint.h>

// Problem constants
#define BB   256      // batch
#define TT   256      // time steps
#define ID   256      // input dim
#define HH   1024     // hidden dim
#define GG   4096     // 4*H gates

// Step-kernel tiling
#define KC          64                 // K chunk
#define NCH         (HH / KC)          // 16 chunks
// smem: A stages 2 x 16KB, B stages 2 x 32KB, pre tile 34KB
#define A_STAGE     16384
#define B_BASE      32768
#define B_STAGE     32768
#define PRE_BASE    98304
#define PRE_ROW     544                // 512 data + 32 pad (bank spread)
#define DYN_SMEM    (PRE_BASE + 64 * PRE_ROW)   // 133,120
// Pre-GEMM smem: single stage, Ahi/Alo 16K + Bhi/Blo 16K
#define PRE_SMEM    65536

typedef unsigned long long ull;

// Scratch (device globals: allocation-free rule)
__device__ float g_pre[(size_t)BB * TT * GG];        // 1 GiB input-gate precompute
__device__ __nv_bfloat16 g_ut_hi[(size_t)GG * HH];   // U^T split hi [4096][1024]
__device__ __nv_bfloat16 g_ut_lo[(size_t)GG * HH];   // U^T split lo
__device__ __nv_bfloat16 g_wt_hi[GG * ID];           // folded W^T split hi
__device__ __nv_bfloat16 g_wt_lo[GG * ID];           // folded W^T split lo
__device__ __nv_bfloat16 g_x_hi[(size_t)BB * TT * ID];   // X split hi
__device__ __nv_bfloat16 g_x_lo[(size_t)BB * TT * ID];   // X split lo
__device__ __nv_bfloat16 g_hbf_hi[2][BB * HH];       // h ping-pong bf16 hi
__device__ __nv_bfloat16 g_hbf_lo[2][BB * HH];       // h ping-pong bf16 lo
__device__ unsigned int g_bar4[4][32];               // per-mt barriers (padded)

// ---------------------------------------------------------------------------
// helpers
// ---------------------------------------------------------------------------
__device__ __forceinline__ float fast_sigmoid(float x) {
    float e = __expf(-x);
    return __fdividef(1.0f, 1.0f + e);
}
__device__ __forceinline__ float fast_tanh(float x) {
    float e = __expf(2.0f * x);
    return 1.0f - __fdividef(2.0f, e + 1.0f);
}
__device__ __forceinline__ void cp_async16(uint32_t dst, const void* src) {
    asm volatile("cp.async.cg.shared.global [%0], [%1], 16;" :: "r"(dst), "l"(src));
}
__device__ __forceinline__ void ldsm_x4(uint32_t* r, uint32_t addr) {
    asm volatile("ldmatrix.sync.aligned.m8n8.x4.shared.b16 {%0,%1,%2,%3}, [%4];"
                 : "=r"(r[0]), "=r"(r[1]), "=r"(r[2]), "=r"(r[3]) : "r"(addr));
}
__device__ __forceinline__ void mma_bf16(float* d, const uint32_t* a, const uint32_t* b) {
    asm volatile("mma.sync.aligned.m16n8k16.row.col.f32.bf16.bf16.f32 "
                 "{%0,%1,%2,%3}, {%4,%5,%6,%7}, {%8,%9}, {%0,%1,%2,%3};"
                 : "+f"(d[0]), "+f"(d[1]), "+f"(d[2]), "+f"(d[3])
                 : "r"(a[0]), "r"(a[1]), "r"(a[2]), "r"(a[3]), "r"(b[0]), "r"(b[1]));
}

// ---------------------------------------------------------------------------
// Kernel A: fold Wy into W row 255, transpose, bf16-split -> g_wt_hi/lo[g][k]
// ---------------------------------------------------------------------------
__global__ void wt_split_kernel(const float* __restrict__ W,
                                const float* __restrict__ Wy) {
    __shared__ float tile[32][33];
    const int kb = blockIdx.x * 32;
    const int gb = blockIdx.y * 32;
    const int tx = threadIdx.x & 31;
    const int ty = threadIdx.x >> 5;
#pragma unroll
    for (int i = 0; i < 32; i += 8) {
        int krow = kb + ty + i;
        float v = W[(size_t)krow * GG + gb + tx];
        if (krow == ID - 1) v += Wy[gb + tx];
        tile[ty + i][tx] = v;
    }
    __syncthreads();
#pragma unroll
    for (int i = 0; i < 32; i += 8) {
        int g = gb + ty + i;
        int k = kb + tx;
        float v = tile[tx][ty + i];
        __nv_bfloat16 hi = __float2bfloat16(v);
        __nv_bfloat16 lo = __float2bfloat16(v - __bfloat162float(hi));
        g_wt_hi[g * ID + k] = hi;
        g_wt_lo[g * ID + k] = lo;
    }
}

// ---------------------------------------------------------------------------
// Kernel B: U^T bf16 split
// ---------------------------------------------------------------------------
__global__ void u_split_kernel(const float* __restrict__ U) {
    __shared__ float tile[32][33];
    const int kb = blockIdx.x * 32;
    const int gb = blockIdx.y * 32;
    const int tx = threadIdx.x & 31;
    const int ty = threadIdx.x >> 5;
#pragma unroll
    for (int i = 0; i < 32; i += 8)
        tile[ty + i][tx] = U[(size_t)(kb + ty + i) * GG + gb + tx];
    __syncthreads();
#pragma unroll
    for (int i = 0; i < 32; i += 8) {
        int g = gb + ty + i;
        int k = kb + tx;
        float v = tile[tx][ty + i];
        __nv_bfloat16 hi = __float2bfloat16(v);
        __nv_bfloat16 lo = __float2bfloat16(v - __bfloat162float(hi));
        g_ut_hi[(size_t)g * HH + k] = hi;
        g_ut_lo[(size_t)g * HH + k] = lo;
    }
}

// ---------------------------------------------------------------------------
// Kernel C: X bf16 split
// ---------------------------------------------------------------------------
__global__ void x_split_kernel(const float* __restrict__ X) {
    size_t i4 = (size_t)blockIdx.x * blockDim.x + threadIdx.x;
    float4 v = *(const float4*)(X + i4 * 4);
    float f[4] = {v.x, v.y, v.z, v.w};
    __nv_bfloat16 hi[4], lo[4];
#pragma unroll
    for (int e = 0; e < 4; ++e) {
        hi[e] = __float2bfloat16(f[e]);
        lo[e] = __float2bfloat16(f[e] - __bfloat162float(hi[e]));
    }
    *(__nv_bfloat162*)(g_x_hi + i4 * 4)     = __nv_bfloat162(hi[0], hi[1]);
    *(__nv_bfloat162*)(g_x_hi + i4 * 4 + 2) = __nv_bfloat162(hi[2], hi[3]);
    *(__nv_bfloat162*)(g_x_lo + i4 * 4)     = __nv_bfloat162(lo[0], lo[1]);
    *(__nv_bfloat162*)(g_x_lo + i4 * 4 + 2) = __nv_bfloat162(lo[2], lo[3]);
}

// ---------------------------------------------------------------------------
// Kernel D: tensorized pre-GEMM (R5 occ-2 version + B ldsm_x4 merge).
// g_pre[m, g] = X[m,:] @ Wf[:, g] + bias[g]; CTA 128m x 128n, 4 K-chunks.
// ---------------------------------------------------------------------------
__global__ __launch_bounds__(256, 2) void pre_gemm_mma(
    const float* __restrict__ bias) {
    extern __shared__ char dsm[];
    const uint32_t sA = (uint32_t)__cvta_generic_to_shared(dsm);
    const uint32_t sB = sA + 32768;

    const int tid = threadIdx.x;
    const int wid = tid >> 5;
    const int lane = tid & 31;
    const int mwarp = wid >> 1;
    const int nwarp = wid & 1;
    const int m0 = blockIdx.y * 128;
    const int n0 = blockIdx.x * 128;

    float acc[2][8][4];
#pragma unroll
    for (int mb = 0; mb < 2; ++mb)
#pragma unroll
        for (int nb = 0; nb < 8; ++nb)
#pragma unroll
            for (int r = 0; r < 4; ++r) acc[mb][nb][r] = 0.f;

    for (int kb = 0; kb < ID / KC; ++kb) {
        const int k0 = kb * KC;
        __syncthreads();
#pragma unroll
        for (int i = 0; i < 8; ++i) {
            int idx = i * 256 + tid;
            int mat = idx >> 10;
            int row = (idx >> 3) & 127;
            int gk = idx & 7;
            const __nv_bfloat16* src = (mat ? g_x_lo : g_x_hi) +
                (size_t)(m0 + row) * ID + k0 + gk * 8;
            uint32_t dst = sA + mat * 16384 + row * 128 + ((gk ^ (row & 7)) << 4);
            cp_async16(dst, src);
        }
#pragma unroll
        for (int i = 0; i < 8; ++i) {
            int idx = i * 256 + tid;
            int mat = idx >> 10;
            int row = (idx >> 3) & 127;
            int gk = idx & 7;
            const __nv_bfloat16* src = (mat ? g_wt_lo : g_wt_hi) +
                (size_t)(n0 + row) * ID + k0 + gk * 8;
            uint32_t dst = sB + mat * 16384 + row * 128 + ((gk ^ (row & 7)) << 4);
            cp_async16(dst, src);
        }
        asm volatile("cp.async.commit_group;" ::: "memory");
        asm volatile("cp.async.wait_group 0;" ::: "memory");
        __syncthreads();

#pragma unroll
        for (int ks = 0; ks < KC / 16; ++ks) {
            uint32_t a_hi[2][4], a_lo[2][4];
#pragma unroll
            for (int mb = 0; mb < 2; ++mb) {
                uint32_t arow = mwarp * 32 + mb * 16 + (lane & 15);
                int gk = ks * 2 + (lane >> 4);
                uint32_t off = arow * 128 + ((gk ^ (arow & 7)) << 4);
                ldsm_x4(a_hi[mb], sA + off);
                ldsm_x4(a_lo[mb], sA + 16384 + off);
            }
#pragma unroll
            for (int nbp = 0; nbp < 4; ++nbp) {
                uint32_t brow = nwarp * 64 + nbp * 16 + (lane & 7) + (lane >> 4) * 8;
                int gk = ks * 2 + ((lane >> 3) & 1);
                uint32_t off = brow * 128 + ((gk ^ (brow & 7)) << 4);
                uint32_t b_hi4[4], b_lo4[4];
                ldsm_x4(b_hi4, sB + off);
                ldsm_x4(b_lo4, sB + 16384 + off);
#pragma unroll
                for (int h = 0; h < 2; ++h) {
#pragma unroll
                    for (int mb = 0; mb < 2; ++mb) {
                        mma_bf16(acc[mb][nbp * 2 + h], a_hi[mb], b_hi4 + h * 2);
                        mma_bf16(acc[mb][nbp * 2 + h], a_hi[mb], b_lo4 + h * 2);
                        mma_bf16(acc[mb][nbp * 2 + h], a_lo[mb], b_hi4 + h * 2);
                    }
                }
            }
        }
    }

    // epilogue: + bias, store fp32
#pragma unroll
    for (int nb = 0; nb < 8; ++nb) {
        const int col = n0 + nwarp * 64 + nb * 8 + (lane & 3) * 2;
        float2 bv = *(const float2*)(bias + col);
#pragma unroll
        for (int mb = 0; mb < 2; ++mb)
#pragma unroll
            for (int rh = 0; rh < 2; ++rh) {
                int row = m0 + mwarp * 32 + mb * 16 + rh * 8 + (lane >> 2);
                float2 o = make_float2(acc[mb][nb][rh * 2] + bv.x,
                                       acc[mb][nb][rh * 2 + 1] + bv.y);
                *(float2*)(g_pre + (size_t)row * GG + col) = o;
            }
    }
}

// ---------------------------------------------------------------------------
// Kernel E: barrier init
// ---------------------------------------------------------------------------
__global__ void bar_init_kernel() {
    if (threadIdx.x < 128)
        ((unsigned int*)g_bar4)[threadIdx.x] = 0u;
}

// ---------------------------------------------------------------------------
// Kernel F: persistent LSTM. 128 CTAs (1/SM), per-mt barriers (32 CTAs each),
// decoupled A/B pipelines, B prefetched across step boundary, pre tile
// prefetched to smem during the MMA loop.
// ---------------------------------------------------------------------------
__global__ __launch_bounds__(256, 1) void lstm_persistent(
    float* __restrict__ hidden,      // [B][T][H]
    float* __restrict__ c_state,     // [B][H]
    float* __restrict__ h_final) {   // [B][H]
    extern __shared__ char dsm[];
    const int tid = threadIdx.x;
    const int wid = tid >> 5;
    const int lane = tid & 31;
    const int jt = blockIdx.x;       // 0..31
    const int mt = blockIdx.y;       // 0..3
    const int mwarp = wid >> 1;      // 0..3
    const int jwarp = wid & 1;       // 0..1
    const uint32_t smem0 = (uint32_t)__cvta_generic_to_shared(dsm);

    // B loader: U^T rows for this jt (step-independent addresses)
    auto issue_B = [&](int c, int s) {
        const int k0 = c * KC;
        const uint32_t sb = smem0 + B_BASE + s * B_STAGE;
#pragma unroll
        for (int i = 0; i < 8; ++i) {
            int idx = i * 256 + tid;
            int mat = idx >> 10;
            int row = (idx >> 3) & 127;
            int gk = idx & 7;
            int grow = (row >> 5) * HH + jt * 32 + (row & 31);
            const __nv_bfloat16* src = (mat ? g_ut_lo : g_ut_hi) +
                (size_t)grow * HH + k0 + gk * 8;
            uint32_t dst = sb + mat * 16384 + row * 128 + ((gk ^ (row & 7)) << 4);
            cp_async16(dst, src);
        }
    };
    // pre tile loader: 64 rows x 4 gates x 32 floats for step t
    auto issue_pre = [&](int t) {
#pragma unroll
        for (int i = 0; i < 8; ++i) {
            int idx = i * 256 + tid;
            int row = idx >> 5;
            int gate = (idx >> 3) & 3;
            int g16 = idx & 7;
            const float* src = g_pre + ((size_t)(mt * 64 + row) * TT + t) * GG +
                               gate * HH + jt * 32 + g16 * 4;
            uint32_t dst = smem0 + PRE_BASE + row * PRE_ROW + gate * 128 + g16 * 16;
            cp_async16(dst, src);
        }
    };

    for (int t = 0; t < TT; ++t) {
        float acc[4][2][4];
#pragma unroll
        for (int g = 0; g < 4; ++g)
#pragma unroll
            for (int nb = 0; nb < 2; ++nb)
#pragma unroll
                for (int r = 0; r < 4; ++r) acc[g][nb][r] = 0.f;

        if (t > 0) {
            const __nv_bfloat16* hphi = g_hbf_hi[(t - 1) & 1];
            const __nv_bfloat16* hplo = g_hbf_lo[(t - 1) & 1];

            auto issue_A = [&](int c, int s) {
                const int k0 = c * KC;
                const uint32_t sb = smem0 + s * A_STAGE;
#pragma unroll
                for (int i = 0; i < 4; ++i) {
                    int idx = i * 256 + tid;
                    int mat = idx >> 9;
                    int row = (idx >> 3) & 63;
                    int gk = idx & 7;
                    const __nv_bfloat16* src = (mat ? hplo : hphi) +
                        (size_t)(mt * 64 + row) * HH + k0 + gk * 8;
                    uint32_t dst = sb + mat * 8192 + row * 128 + ((gk ^ (row & 7)) << 4);
                    cp_async16(dst, src);
                }
            };

            // A chunk 0 (B chunk 0 was prefetched across the step boundary;
            // its completion is covered by this wait_group 0 too).
            issue_A(0, 0);
            asm volatile("cp.async.commit_group;" ::: "memory");
            asm volatile("cp.async.wait_group 0;" ::: "memory");
            __syncthreads();

            const uint32_t arow = mwarp * 16 + (lane & 15);
            const uint32_t brow_base = jwarp * 16 + (lane & 7) + (lane >> 4) * 8;

            for (int c = 0; c < NCH; ++c) {
                const int s = c & 1;
                if (c + 1 < NCH) {
                    issue_A(c + 1, s ^ 1);
                    issue_B(c + 1, s ^ 1);
                    if (c == 1) issue_pre(t);   // hidden under chunk-1 compute
                } else if (t + 1 < TT) {
                    issue_B(0, 0);    // next step's chunk 0 (U step-invariant)
                }
                asm volatile("cp.async.commit_group;" ::: "memory");

                const uint32_t sA = smem0 + s * A_STAGE;
                const uint32_t sB = smem0 + B_BASE + s * B_STAGE;
#pragma unroll
                for (int ks = 0; ks < KC / 16; ++ks) {
                    uint32_t a_hi[4], a_lo[4];
                    {
                        int gk = ks * 2 + (lane >> 4);
                        uint32_t off = arow * 128 + ((gk ^ (arow & 7)) << 4);
                        ldsm_x4(a_hi, sA + off);
                        ldsm_x4(a_lo, sA + 8192 + off);
                    }
#pragma unroll
                    for (int g = 0; g < 4; ++g) {
                        uint32_t row = g * 32 + brow_base;
                        int gk = ks * 2 + ((lane >> 3) & 1);
                        uint32_t off = row * 128 + ((gk ^ (row & 7)) << 4);
                        uint32_t b_hi4[4], b_lo4[4];
                        ldsm_x4(b_hi4, sB + off);
                        ldsm_x4(b_lo4, sB + 16384 + off);
#pragma unroll
                        for (int nb = 0; nb < 2; ++nb) {
                            mma_bf16(acc[g][nb], a_hi, b_hi4 + nb * 2);
                            mma_bf16(acc[g][nb], a_hi, b_lo4 + nb * 2);
                            mma_bf16(acc[g][nb], a_lo, b_hi4 + nb * 2);
                        }
                    }
                }
                if (c + 1 < NCH) {
                    asm volatile("cp.async.wait_group 0;" ::: "memory");
                    __syncthreads();
                }
                // final chunk: skip wait — pending B prefetch completes during
                // the barrier spin; waited at next step's wait_group 0.
            }
        } else {
            // t == 0: prefetch B chunk 0 for step 1 + pre tile for t=0.
            issue_B(0, 0);
            issue_pre(0);
            asm volatile("cp.async.commit_group;" ::: "memory");
            asm volatile("cp.async.wait_group 0;" ::: "memory");
            __syncthreads();
        }

        // ---- fused cell-update epilogue (pre read from smem) ----
        const int b_base = mt * 64 + mwarp * 16 + (lane >> 2);
#pragma unroll
        for (int rh = 0; rh < 2; ++rh) {
            const int b = b_base + rh * 8;
            const char* prs = dsm + PRE_BASE +
                (size_t)(mwarp * 16 + rh * 8 + (lane >> 2)) * PRE_ROW;
            float* crow = c_state + (size_t)b * HH;
            float* hrow = hidden + ((size_t)b * TT + t) * HH;
            __nv_bfloat16* bh = g_hbf_hi[t & 1] + (size_t)b * HH;
            __nv_bfloat16* bl = g_hbf_lo[t & 1] + (size_t)b * HH;
#pragma unroll
            for (int nb = 0; nb < 2; ++nb) {
                const int jcol = jwarp * 16 + nb * 8 + (lane & 3) * 2;
                const int j = jt * 32 + jcol;
                float2 pi = *(const float2*)(prs + 0 * 128 + jcol * 4);
                float2 pf = *(const float2*)(prs + 1 * 128 + jcol * 4);
                float2 pg = *(const float2*)(prs + 2 * 128 + jcol * 4);
                float2 po = *(const float2*)(prs + 3 * 128 + jcol * 4);
                float2 co = (t > 0) ? *(const float2*)(crow + j)
                                    : make_float2(0.f, 0.f);
                const int r0 = rh * 2;
                float i0 = fast_sigmoid(acc[0][nb][r0]     + pi.x);
                float i1 = fast_sigmoid(acc[0][nb][r0 + 1] + pi.y);
                float f0 = fast_sigmoid(acc[1][nb][r0]     + pf.x);
                float f1 = fast_sigmoid(acc[1][nb][r0 + 1] + pf.y);
                float g0 = fast_tanh(acc[2][nb][r0]     + pg.x);
                float g1 = fast_tanh(acc[2][nb][r0 + 1] + pg.y);
                float o0 = fast_sigmoid(acc[3][nb][r0]     + po.x);
                float o1 = fast_sigmoid(acc[3][nb][r0 + 1] + po.y);
                float cn0 = f0 * co.x + i0 * g0;
                float cn1 = f1 * co.y + i1 * g1;
                float hn0 = o0 * fast_tanh(cn0);
                float hn1 = o1 * fast_tanh(cn1);
                *(float2*)(crow + j) = make_float2(cn0, cn1);
                *(float2*)(hrow + j) = make_float2(hn0, hn1);
                __nv_bfloat16 h0h = __float2bfloat16(hn0);
                __nv_bfloat16 h1h = __float2bfloat16(hn1);
                __nv_bfloat16 h0l = __float2bfloat16(hn0 - __bfloat162float(h0h));
                __nv_bfloat16 h1l = __float2bfloat16(hn1 - __bfloat162float(h1h));
                *(__nv_bfloat162*)(bh + j) = __nv_bfloat162(h0h, h1h);
                *(__nv_bfloat162*)(bl + j) = __nv_bfloat162(h0l, h1l);
                if (t == TT - 1)
                    *(float2*)(h_final + (size_t)b * HH + j) = make_float2(hn0, hn1);
            }
        }

        // ---- per-mt device barrier (32 CTAs) ----
        if (t < TT - 1) {
            __threadfence();
            __syncthreads();
            if (tid == 0) {
                atomicAdd(&g_bar4[mt][0], 1u);
                const unsigned target = 32u * (unsigned)(t + 1);
                while (atomicAdd(&g_bar4[mt][0], 0u) < target) {}
            }
            __syncthreads();
            __threadfence();
        }
    }
}

// ---------------------------------------------------------------------------
// Kernel G: y_pred[b] = h_final[b,:] . fc_w + fc_b
// ---------------------------------------------------------------------------
__global__ void fc_kernel(const float* __restrict__ h_final,
                          const float* __restrict__ fc_w,
                          const float* __restrict__ fc_b,
                          float* __restrict__ y_pred) {
    int b = blockIdx.x;
    int tid = threadIdx.x;
    float s = 0.f;
    for (int k = tid; k < HH; k += 256)
        s += h_final[b * HH + k] * fc_w[k];
#pragma unroll
    for (int off = 16; off > 0; off >>= 1)
        s += __shfl_down_sync(0xffffffffu, s, off);
    __shared__ float red[8];
    if ((tid & 31) == 0) red[tid >> 5] = s;
    __syncthreads();
    if (tid == 0) {
        float tot = 0.f;
#pragma unroll
        for (int w = 0; w < 8; ++w) tot += red[w];
        y_pred[b] = tot + fc_b[0];
    }
}

// ---------------------------------------------------------------------------
extern "C" void kernel_launch(void* const* d_in, const int* in_sizes, int n_in,
                              void* d_out, int out_size) {
    const float* X    = (const float*)d_in[0];
    const float* W    = (const float*)d_in[1];
    const float* U    = (const float*)d_in[2];
    const float* bias = (const float*)d_in[3];
    const float* Wy   = (const float*)d_in[4];
    const float* fc_w = (const float*)d_in[5];
    const float* fc_b = (const float*)d_in[6];

    float* out = (float*)d_out;
    // output layout: y_pred[256] | hidden_seq[B*T*H] | h_t[B*H] | c_t[B*H]
    float* y_pred  = out;
    float* hidden  = out + 256;
    float* h_final = hidden + (size_t)BB * TT * HH;
    float* c_state = h_final + (size_t)BB * HH;

    cudaFuncSetAttribute(lstm_persistent, cudaFuncAttributeMaxDynamicSharedMemorySize,
                         DYN_SMEM);
    cudaFuncSetAttribute(pre_gemm_mma, cudaFuncAttributeMaxDynamicSharedMemorySize,
                         PRE_SMEM);

    wt_split_kernel<<<dim3(ID / 32, GG / 32), 256>>>(W, Wy);
    u_split_kernel<<<dim3(HH / 32, GG / 32), 256>>>(U);
    x_split_kernel<<<(BB * TT * ID) / 4 / 256, 256>>>(X);
    pre_gemm_mma<<<dim3(GG / 128, (BB * TT) / 128), 256, PRE_SMEM>>>(bias);
    bar_init_kernel<<<1, 128>>>();
    lstm_persistent<<<dim3(HH / 32, BB / 64), 256, DYN_SMEM>>>(hidden, c_state,
                                                               h_final);
    fc_kernel<<<BB, 256>>>(h_final, fc_w, fc_b, y_pred);
}